// round 12
// baseline (speedup 1.0000x reference)
#include <cuda_runtime.h>
#include <math.h>
#include <stdint.h>

// Problem constants (fixed by dataset)
#define NT     256    // tokens per block tile
#define KC     32     // K chunk
#define DDIM   1024   // hidden dim
#define NE     64     // experts
#define NCHUNK (DDIM / KC)
#define THREADS 512

// Shared-memory geometry (floats)
#define AS_STRIDE 36                  // 144B rows: 16B-aligned for cp.async, 8B for LDS.64
#define AS_BUF    (NT * AS_STRIDE)    // 9216 floats per buffer
#define BS_STRIDE 132                 // 33 float4 per k-pair row (bank-shifted)
#define BS_ROWS   (KC / 2)            // 16 k-pairs
#define BS_BUF    (BS_ROWS * BS_STRIDE)
#define SMEM_FLOATS (2 * AS_BUF + 2 * BS_BUF)   // 22656 floats = 90624 B

// ---- f32x2 packed-math helpers (Blackwell sm_100+) ----
__device__ __forceinline__ unsigned long long dup2(float x) {
    unsigned long long r;
    asm("mov.b64 %0, {%1, %1};" : "=l"(r) : "f"(x));
    return r;
}
__device__ __forceinline__ void up2(unsigned long long v, float& lo, float& hi) {
    asm("mov.b64 {%0, %1}, %2;" : "=f"(lo), "=f"(hi) : "l"(v));
}
__device__ __forceinline__ void ffma2(unsigned long long& acc, unsigned long long a,
                                      unsigned long long b) {
    asm("fma.rn.f32x2 %0, %1, %2, %3;" : "=l"(acc) : "l"(a), "l"(b), "l"(acc));
}
__device__ __forceinline__ void cpa16(uint32_t dst, const float* src) {
    asm volatile("cp.async.cg.shared.global [%0], [%1], 16;" :: "r"(dst), "l"(src));
}

// Write one float4 of W (expert e, local k = q*4..q*4+3) into the interleaved,
// bank-permuted B buffer. Layout per k-pair row kp:
//   float4 slot 'col' = {B[2kp][2P], B[2kp][2P+1], B[2kp+1][2P], B[2kp+1][2P+1]}
//   with col = (P&3)*8 + (P>>2)  (thread tx reads slots j*8+tx -> pair P=4*tx+j,
//   i.e. experts 8*tx+2j, 8*tx+2j+1, matching acc[i][j])
__device__ __forceinline__ void stsB(float* Bp, int e, int q, float4 v) {
    int P = e >> 1;
    int col = (P & 3) * 8 + (P >> 2);
    float* base = Bp + col * 4 + (e & 1);
    base[(q * 2 + 0) * BS_STRIDE + 0] = v.x;   // k = 4q
    base[(q * 2 + 0) * BS_STRIDE + 2] = v.y;   // k = 4q+1
    base[(q * 2 + 1) * BS_STRIDE + 0] = v.z;   // k = 4q+2
    base[(q * 2 + 1) * BS_STRIDE + 2] = v.w;   // k = 4q+3
}

__global__ __launch_bounds__(THREADS, 2)
void router_kernel(const float* __restrict__ A,
                   const int*   __restrict__ t,
                   const float* __restrict__ W,
                   const float* __restrict__ bg,
                   float*       __restrict__ out)
{
    extern __shared__ float sm[];
    float* Asm = sm;                 // [2][NT][AS_STRIDE]
    float* Bsm = sm + 2 * AS_BUF;    // [2][BS_ROWS][BS_STRIDE]

    const int tid  = threadIdx.x;
    const int tx   = tid & 7;        // expert group: experts tx*8 .. tx*8+7
    const int ty   = tid >> 3;       // token sub-index 0..63; tokens i*64+ty, i=0..3
    const int tok0 = blockIdx.x * NT;
    const float* Ab = A + (size_t)tok0 * DDIM;

    uint32_t sbase;
    asm("{ .reg .u64 x; cvta.to.shared.u64 x, %1; cvt.u32.u64 %0, x; }"
        : "=r"(sbase) : "l"(sm));

    // accumulators: 4 tokens x 4 expert-pairs, packed f32x2
    unsigned long long acc[4][4];
    #pragma unroll
    for (int i = 0; i < 4; i++)
        #pragma unroll
        for (int j = 0; j < 4; j++) acc[i][j] = 0ull;

    // B staging indices: 512 threads cover 64 experts x 8 quads exactly
    const int eB = tid >> 3, qB = tid & 7;

    // ---------- prologue: stage chunk 0 ----------
    #pragma unroll
    for (int r = 0; r < 4; r++) {
        int f = tid + r * THREADS;
        int tl = f >> 3, q = f & 7;
        uint32_t dst = sbase + (uint32_t)(tl * AS_STRIDE + q * 4) * 4u;
        cpa16(dst, Ab + (size_t)tl * DDIM + q * 4);
    }
    asm volatile("cp.async.commit_group;" ::: "memory");
    {
        float4 b0 = *reinterpret_cast<const float4*>(W + (size_t)eB * DDIM + qB * 4);
        stsB(Bsm, eB, qB, b0);
    }
    asm volatile("cp.async.wait_group 0;" ::: "memory");
    __syncthreads();

    // ---------- main loop: double-buffered ----------
    #pragma unroll 1
    for (int c = 0; c < NCHUNK; c++) {
        const int buf = c & 1;
        float4 bv;
        const bool more = (c + 1 < NCHUNK);
        if (more) {
            const int k0n = (c + 1) * KC;
            #pragma unroll
            for (int r = 0; r < 4; r++) {
                int f = tid + r * THREADS;
                int tl = f >> 3, q = f & 7;
                uint32_t dst = sbase +
                    (uint32_t)((buf ^ 1) * AS_BUF + tl * AS_STRIDE + q * 4) * 4u;
                cpa16(dst, Ab + (size_t)tl * DDIM + k0n + q * 4);
            }
            asm volatile("cp.async.commit_group;" ::: "memory");
            bv = *reinterpret_cast<const float4*>(W + (size_t)eB * DDIM + k0n + qB * 4);
        }

        // compute this chunk: 16 k-pairs, j-split to cap live registers
        const float* Ap = Asm + buf * AS_BUF;
        const float* Bp = Bsm + buf * BS_BUF;
        #pragma unroll 4
        for (int kp = 0; kp < BS_ROWS; kp++) {
            float2 af[4];
            #pragma unroll
            for (int i = 0; i < 4; i++)
                af[i] = *reinterpret_cast<const float2*>(
                    Ap + (i * 64 + ty) * AS_STRIDE + kp * 2);

            {   // expert pairs j=0,1
                ulonglong2 b0 = *reinterpret_cast<const ulonglong2*>(
                    Bp + kp * BS_STRIDE + (0 * 8 + tx) * 4);
                ulonglong2 b1 = *reinterpret_cast<const ulonglong2*>(
                    Bp + kp * BS_STRIDE + (1 * 8 + tx) * 4);
                #pragma unroll
                for (int i = 0; i < 4; i++) {
                    unsigned long long a0 = dup2(af[i].x);
                    unsigned long long a1 = dup2(af[i].y);
                    ffma2(acc[i][0], a0, b0.x);
                    ffma2(acc[i][1], a0, b1.x);
                    ffma2(acc[i][0], a1, b0.y);
                    ffma2(acc[i][1], a1, b1.y);
                }
            }
            {   // expert pairs j=2,3
                ulonglong2 b2 = *reinterpret_cast<const ulonglong2*>(
                    Bp + kp * BS_STRIDE + (2 * 8 + tx) * 4);
                ulonglong2 b3 = *reinterpret_cast<const ulonglong2*>(
                    Bp + kp * BS_STRIDE + (3 * 8 + tx) * 4);
                #pragma unroll
                for (int i = 0; i < 4; i++) {
                    unsigned long long a0 = dup2(af[i].x);
                    unsigned long long a1 = dup2(af[i].y);
                    ffma2(acc[i][2], a0, b2.x);
                    ffma2(acc[i][3], a0, b3.x);
                    ffma2(acc[i][2], a1, b2.y);
                    ffma2(acc[i][3], a1, b3.y);
                }
            }
        }

        if (more) {
            float* Bn = Bsm + (buf ^ 1) * BS_BUF;
            stsB(Bn, eB, qB, bv);
            asm volatile("cp.async.wait_group 0;" ::: "memory");
        }
        __syncthreads();
    }

    // ---------------- epilogue: softmax -> floor -> hard cap -> top-2 ----------------
    const int   bidx = tok0 >> 12;                 // 4096 tokens per batch
    const float tn   = (float)t[bidx] / 1000.0f;
    const float cap  = 0.5f + 1.1f * tn;           // CAP_LOW + (CAP_HIGH+CAP_LOW)*t_norm

    float bgl[8];
    #pragma unroll
    for (int j = 0; j < 8; j++) bgl[j] = bg[tx * 8 + j];

    const unsigned FULL = 0xffffffffu;

    #pragma unroll
    for (int i = 0; i < 4; i++) {
        float v[8];
        #pragma unroll
        for (int j = 0; j < 4; j++) {
            float lo, hi; up2(acc[i][j], lo, hi);
            v[2 * j]     = lo + bgl[2 * j];
            v[2 * j + 1] = hi + bgl[2 * j + 1];
        }
        // softmax over 64 (8 local + 8-lane group reduce)
        float m = v[0];
        #pragma unroll
        for (int j = 1; j < 8; j++) m = fmaxf(m, v[j]);
        #pragma unroll
        for (int off = 4; off > 0; off >>= 1)
            m = fmaxf(m, __shfl_xor_sync(FULL, m, off));
        float s = 0.0f;
        #pragma unroll
        for (int j = 0; j < 8; j++) { v[j] = expf(v[j] - m); s += v[j]; }
        #pragma unroll
        for (int off = 4; off > 0; off >>= 1)
            s += __shfl_xor_sync(FULL, s, off);
        float sinv = 1.0f / s;
        // routing floor: (1-alpha)*p + alpha/E, alpha = 0.15
        #pragma unroll
        for (int j = 0; j < 8; j++) {
            float p = v[j] * sinv;
            v[j] = fmaf(0.85f, p, 0.00234375f);
        }
        // hard cap (faithful vector form)
        float h[8];
        float es = 0.0f, hs = 0.0f;
        #pragma unroll
        for (int j = 0; j < 8; j++) {
            float ex = fmaxf(v[j] - cap, 0.0f);
            float cp = v[j] - ex;
            float hh = fmaxf(cap - cp, 0.0f);
            es += ex; hs += hh; v[j] = cp; h[j] = hh;
        }
        #pragma unroll
        for (int off = 4; off > 0; off >>= 1) {
            es += __shfl_xor_sync(FULL, es, off);
            hs += __shfl_xor_sync(FULL, hs, off);
        }
        hs = fmaxf(hs, 1e-8f);
        float hsinv = 1.0f / hs;
        #pragma unroll
        for (int j = 0; j < 8; j++) v[j] = v[j] + es * (h[j] * hsinv);

        // local top-2 (strict > keeps lowest index on ties, matching jax top_k)
        float v1 = -1.0f, v2 = -1.0f; int i1 = 1 << 30, i2 = 1 << 30;
        #pragma unroll
        for (int j = 0; j < 8; j++) {
            float f = v[j]; int idx = tx * 8 + j;
            if (f > v1)      { v2 = v1; i2 = i1; v1 = f; i1 = idx; }
            else if (f > v2) { v2 = f; i2 = idx; }
        }
        // merge across the 8-lane group (tie -> lower expert index)
        #pragma unroll
        for (int off = 4; off > 0; off >>= 1) {
            float ov1 = __shfl_xor_sync(FULL, v1, off);
            int   oi1 = __shfl_xor_sync(FULL, i1, off);
            float ov2 = __shfl_xor_sync(FULL, v2, off);
            int   oi2 = __shfl_xor_sync(FULL, i2, off);
            float n1v, n2v; int n1i, n2i;
            bool mine = (v1 > ov1) || (v1 == ov1 && i1 < oi1);
            if (mine) {
                n1v = v1; n1i = i1;
                bool s2 = (v2 > ov1) || (v2 == ov1 && i2 < oi1);
                n2v = s2 ? v2 : ov1; n2i = s2 ? i2 : oi1;
            } else {
                n1v = ov1; n1i = oi1;
                bool s2 = (v1 > ov2) || (v1 == ov2 && i1 < oi2);
                n2v = s2 ? v1 : ov2; n2i = s2 ? i1 : oi2;
            }
            v1 = n1v; i1 = n1i; v2 = n2v; i2 = n2i;
        }

        // write sparse gates: this lane owns experts tx*8..tx*8+7 of this token
        int token = tok0 + i * 64 + ty;
        float o[8];
        #pragma unroll
        for (int j = 0; j < 8; j++) {
            int idx = tx * 8 + j;
            o[j] = (idx == i1) ? v1 : ((idx == i2) ? v2 : 0.0f);
        }
        float4* op = reinterpret_cast<float4*>(out + (size_t)token * NE + tx * 8);
        op[0] = make_float4(o[0], o[1], o[2], o[3]);
        op[1] = make_float4(o[4], o[5], o[6], o[7]);
    }
}

extern "C" void kernel_launch(void* const* d_in, const int* in_sizes, int n_in,
                              void* d_out, int out_size) {
    const float* tokens = (const float*)d_in[0];   // (B,N,D) f32
    const int*   t      = (const int*)d_in[1];     // (B,) i32
    const float* W      = (const float*)d_in[2];   // (E,D) f32
    const float* bg     = (const float*)d_in[3];   // (E,) f32
    float*       out    = (float*)d_out;           // (B,N,E) f32

    const size_t smem_bytes = (size_t)SMEM_FLOATS * sizeof(float);  // 90624 B
    cudaFuncSetAttribute(router_kernel,
                         cudaFuncAttributeMaxDynamicSharedMemorySize,
                         (int)smem_bytes);

    int n_tokens = in_sizes[0] / DDIM;             // 65536
    dim3 grid(n_tokens / NT);                      // 256 blocks
    router_kernel<<<grid, THREADS, smem_bytes>>>(tokens, t, W, bg, out);
}

// round 13
// speedup vs baseline: 1.9437x; 1.9437x over previous
#include <cuda_runtime.h>
#include <math.h>
#include <stdint.h>

// Problem constants (fixed by dataset)
#define NT     256    // tokens per block tile
#define KC     32     // K chunk
#define DDIM   1024   // hidden dim
#define NE     64     // experts
#define NCHUNK (DDIM / KC)

// Shared-memory geometry (floats)
#define AS_STRIDE 36                  // 144B rows: 16B-aligned for cp.async, 8B for LDS.64
#define AS_BUF    (NT * AS_STRIDE)    // 9216 floats per buffer
#define BS_STRIDE 132                 // 33 float4 per k-pair row (bank-shifted)
#define BS_ROWS   (KC / 2)            // 16 k-pairs
#define BS_BUF    (BS_ROWS * BS_STRIDE)
#define SMEM_FLOATS (2 * AS_BUF + 2 * BS_BUF)   // 22656 floats = 90624 B

// ---- f32x2 packed-math helpers (Blackwell sm_100+) ----
__device__ __forceinline__ unsigned long long dup2(float x) {
    unsigned long long r;
    asm("mov.b64 %0, {%1, %1};" : "=l"(r) : "f"(x));
    return r;
}
__device__ __forceinline__ void up2(unsigned long long v, float& lo, float& hi) {
    asm("mov.b64 {%0, %1}, %2;" : "=f"(lo), "=f"(hi) : "l"(v));
}
__device__ __forceinline__ void ffma2(unsigned long long& acc, unsigned long long a,
                                      unsigned long long b) {
    asm("fma.rn.f32x2 %0, %1, %2, %3;" : "=l"(acc) : "l"(a), "l"(b), "l"(acc));
}
__device__ __forceinline__ void cpa16(uint32_t dst, const float* src) {
    asm volatile("cp.async.cg.shared.global [%0], [%1], 16;" :: "r"(dst), "l"(src));
}

// Write one float4 of W (expert e, local k = q*4..q*4+3) into the interleaved,
// bank-permuted B buffer. Layout per k-pair row kp:
//   float4 slot 'col' = {B[2kp][2P], B[2kp][2P+1], B[2kp+1][2P], B[2kp+1][2P+1]}
//   with col = (P&3)*8 + (P>>2)  (thread tx reads slots j*8+tx -> pair P=4*tx+j,
//   i.e. experts 8*tx+2j, 8*tx+2j+1, matching acc[i][j])
__device__ __forceinline__ void stsB(float* Bp, int e, int q, float4 v) {
    int P = e >> 1;
    int col = (P & 3) * 8 + (P >> 2);
    float* base = Bp + col * 4 + (e & 1);
    base[(q * 2 + 0) * BS_STRIDE + 0] = v.x;   // k = 4q
    base[(q * 2 + 0) * BS_STRIDE + 2] = v.y;   // k = 4q+1
    base[(q * 2 + 1) * BS_STRIDE + 0] = v.z;   // k = 4q+2
    base[(q * 2 + 1) * BS_STRIDE + 2] = v.w;   // k = 4q+3
}

__global__ __launch_bounds__(256, 2)
void router_kernel(const float* __restrict__ A,
                   const int*   __restrict__ t,
                   const float* __restrict__ W,
                   const float* __restrict__ bg,
                   float*       __restrict__ out)
{
    extern __shared__ float sm[];
    float* Asm = sm;                 // [2][NT][AS_STRIDE]
    float* Bsm = sm + 2 * AS_BUF;    // [2][BS_ROWS][BS_STRIDE]

    const int tid  = threadIdx.x;
    const int tx   = tid & 7;        // expert group: experts tx*8 .. tx*8+7
    const int ty   = tid >> 3;       // token sub-index 0..31
    const int tok0 = blockIdx.x * NT;
    const float* Ab = A + (size_t)tok0 * DDIM;

    uint32_t sbase;
    asm("{ .reg .u64 x; cvta.to.shared.u64 x, %1; cvt.u32.u64 %0, x; }"
        : "=r"(sbase) : "l"(sm));

    unsigned long long acc[8][4];
    #pragma unroll
    for (int i = 0; i < 8; i++)
        #pragma unroll
        for (int j = 0; j < 4; j++) acc[i][j] = 0ull;

    // ---------- prologue: stage chunk 0 ----------
    #pragma unroll
    for (int r = 0; r < 8; r++) {
        int f = tid + r * 256;
        int tl = f >> 3, q = f & 7;
        uint32_t dst = sbase + (uint32_t)(tl * AS_STRIDE + q * 4) * 4u;
        cpa16(dst, Ab + (size_t)tl * DDIM + q * 4);
    }
    asm volatile("cp.async.commit_group;" ::: "memory");
    {
        int e0 = tid >> 3,         q0 = tid & 7;
        int e1 = (tid >> 3) + 32,  q1 = tid & 7;
        float4 b0 = *reinterpret_cast<const float4*>(W + (size_t)e0 * DDIM + q0 * 4);
        float4 b1 = *reinterpret_cast<const float4*>(W + (size_t)e1 * DDIM + q1 * 4);
        stsB(Bsm, e0, q0, b0);
        stsB(Bsm, e1, q1, b1);
    }
    asm volatile("cp.async.wait_group 0;" ::: "memory");
    __syncthreads();

    // ---------- main loop: double-buffered chunks, B software-pipelined ----------
    #pragma unroll 1
    for (int c = 0; c < NCHUNK; c++) {
        const int buf = c & 1;
        float4 bv0, bv1;
        const int e0 = tid >> 3,        q0 = tid & 7;
        const int e1 = (tid >> 3) + 32, q1 = tid & 7;
        const bool more = (c + 1 < NCHUNK);
        if (more) {
            const int k0n = (c + 1) * KC;
            #pragma unroll
            for (int r = 0; r < 8; r++) {
                int f = tid + r * 256;
                int tl = f >> 3, q = f & 7;
                uint32_t dst = sbase +
                    (uint32_t)((buf ^ 1) * AS_BUF + tl * AS_STRIDE + q * 4) * 4u;
                cpa16(dst, Ab + (size_t)tl * DDIM + k0n + q * 4);
            }
            asm volatile("cp.async.commit_group;" ::: "memory");
            bv0 = *reinterpret_cast<const float4*>(W + (size_t)e0 * DDIM + k0n + q0 * 4);
            bv1 = *reinterpret_cast<const float4*>(W + (size_t)e1 * DDIM + k0n + q1 * 4);
        }

        // compute this chunk: 16 k-pairs, B loads pipelined one kp ahead
        const float* Ap = Asm + buf * AS_BUF + ty * AS_STRIDE;
        const float* Bp = Bsm + buf * BS_BUF + tx * 4;
        ulonglong2 bc0, bc1, bc2, bc3;     // current kp's B (4 expert-pairs x 2 k)
        bc0 = *reinterpret_cast<const ulonglong2*>(Bp + 0 * 32);
        bc1 = *reinterpret_cast<const ulonglong2*>(Bp + 1 * 32);
        bc2 = *reinterpret_cast<const ulonglong2*>(Bp + 2 * 32);
        bc3 = *reinterpret_cast<const ulonglong2*>(Bp + 3 * 32);
        #pragma unroll
        for (int kp = 0; kp < BS_ROWS; kp++) {
            ulonglong2 bn0, bn1, bn2, bn3;
            if (kp + 1 < BS_ROWS) {
                const float* Bq = Bp + (kp + 1) * BS_STRIDE;
                bn0 = *reinterpret_cast<const ulonglong2*>(Bq + 0 * 32);
                bn1 = *reinterpret_cast<const ulonglong2*>(Bq + 1 * 32);
                bn2 = *reinterpret_cast<const ulonglong2*>(Bq + 2 * 32);
                bn3 = *reinterpret_cast<const ulonglong2*>(Bq + 3 * 32);
            }
            #pragma unroll
            for (int i = 0; i < 8; i++) {
                float2 af = *reinterpret_cast<const float2*>(
                    Ap + i * (32 * AS_STRIDE) + kp * 2);
                unsigned long long a0 = dup2(af.x);
                unsigned long long a1 = dup2(af.y);
                ffma2(acc[i][0], a0, bc0.x);
                ffma2(acc[i][1], a0, bc1.x);
                ffma2(acc[i][2], a0, bc2.x);
                ffma2(acc[i][3], a0, bc3.x);
                ffma2(acc[i][0], a1, bc0.y);
                ffma2(acc[i][1], a1, bc1.y);
                ffma2(acc[i][2], a1, bc2.y);
                ffma2(acc[i][3], a1, bc3.y);
            }
            if (kp + 1 < BS_ROWS) { bc0 = bn0; bc1 = bn1; bc2 = bn2; bc3 = bn3; }
        }

        if (more) {
            float* Bn = Bsm + (buf ^ 1) * BS_BUF;
            stsB(Bn, e0, q0, bv0);
            stsB(Bn, e1, q1, bv1);
            asm volatile("cp.async.wait_group 0;" ::: "memory");
        }
        __syncthreads();
    }

    // ---------------- epilogue: softmax -> floor -> hard cap -> top-2 ----------------
    const int   bidx = tok0 >> 12;                 // 4096 tokens per batch
    const float tn   = (float)t[bidx] / 1000.0f;
    const float cap  = 0.5f + 1.1f * tn;           // CAP_LOW + (CAP_HIGH+CAP_LOW)*t_norm

    float bgl[8];
    #pragma unroll
    for (int j = 0; j < 8; j++) bgl[j] = bg[tx * 8 + j];

    const unsigned FULL = 0xffffffffu;

    #pragma unroll
    for (int i = 0; i < 8; i++) {
        float v[8];
        #pragma unroll
        for (int j = 0; j < 4; j++) {
            float lo, hi; up2(acc[i][j], lo, hi);
            v[2 * j]     = lo + bgl[2 * j];
            v[2 * j + 1] = hi + bgl[2 * j + 1];
        }
        // softmax over 64 (8 local + 8-lane group reduce)
        float m = v[0];
        #pragma unroll
        for (int j = 1; j < 8; j++) m = fmaxf(m, v[j]);
        #pragma unroll
        for (int off = 4; off > 0; off >>= 1)
            m = fmaxf(m, __shfl_xor_sync(FULL, m, off));
        float s = 0.0f;
        #pragma unroll
        for (int j = 0; j < 8; j++) { v[j] = expf(v[j] - m); s += v[j]; }
        #pragma unroll
        for (int off = 4; off > 0; off >>= 1)
            s += __shfl_xor_sync(FULL, s, off);
        float sinv = 1.0f / s;
        // routing floor: (1-alpha)*p + alpha/E, alpha = 0.15
        #pragma unroll
        for (int j = 0; j < 8; j++) {
            float p = v[j] * sinv;
            v[j] = fmaf(0.85f, p, 0.00234375f);
        }
        // hard cap (faithful vector form)
        float h[8];
        float es = 0.0f, hs = 0.0f;
        #pragma unroll
        for (int j = 0; j < 8; j++) {
            float ex = fmaxf(v[j] - cap, 0.0f);
            float cp = v[j] - ex;
            float hh = fmaxf(cap - cp, 0.0f);
            es += ex; hs += hh; v[j] = cp; h[j] = hh;
        }
        #pragma unroll
        for (int off = 4; off > 0; off >>= 1) {
            es += __shfl_xor_sync(FULL, es, off);
            hs += __shfl_xor_sync(FULL, hs, off);
        }
        hs = fmaxf(hs, 1e-8f);
        float hsinv = 1.0f / hs;
        #pragma unroll
        for (int j = 0; j < 8; j++) v[j] = v[j] + es * (h[j] * hsinv);

        // local top-2 (strict > keeps lowest index on ties, matching jax top_k)
        float v1 = -1.0f, v2 = -1.0f; int i1 = 1 << 30, i2 = 1 << 30;
        #pragma unroll
        for (int j = 0; j < 8; j++) {
            float f = v[j]; int idx = tx * 8 + j;
            if (f > v1)      { v2 = v1; i2 = i1; v1 = f; i1 = idx; }
            else if (f > v2) { v2 = f; i2 = idx; }
        }
        // merge across the 8-lane group (tie -> lower expert index)
        #pragma unroll
        for (int off = 4; off > 0; off >>= 1) {
            float ov1 = __shfl_xor_sync(FULL, v1, off);
            int   oi1 = __shfl_xor_sync(FULL, i1, off);
            float ov2 = __shfl_xor_sync(FULL, v2, off);
            int   oi2 = __shfl_xor_sync(FULL, i2, off);
            float n1v, n2v; int n1i, n2i;
            bool mine = (v1 > ov1) || (v1 == ov1 && i1 < oi1);
            if (mine) {
                n1v = v1; n1i = i1;
                bool s2 = (v2 > ov1) || (v2 == ov1 && i2 < oi1);
                n2v = s2 ? v2 : ov1; n2i = s2 ? i2 : oi1;
            } else {
                n1v = ov1; n1i = oi1;
                bool s2 = (v1 > ov2) || (v1 == ov2 && i1 < oi2);
                n2v = s2 ? v1 : ov2; n2i = s2 ? i1 : oi2;
            }
            v1 = n1v; i1 = n1i; v2 = n2v; i2 = n2i;
        }

        // write sparse gates: this lane owns experts tx*8..tx*8+7 of this token
        int token = tok0 + i * 32 + ty;
        float o[8];
        #pragma unroll
        for (int j = 0; j < 8; j++) {
            int idx = tx * 8 + j;
            o[j] = (idx == i1) ? v1 : ((idx == i2) ? v2 : 0.0f);
        }
        float4* op = reinterpret_cast<float4*>(out + (size_t)token * NE + tx * 8);
        op[0] = make_float4(o[0], o[1], o[2], o[3]);
        op[1] = make_float4(o[4], o[5], o[6], o[7]);
    }
}

extern "C" void kernel_launch(void* const* d_in, const int* in_sizes, int n_in,
                              void* d_out, int out_size) {
    const float* tokens = (const float*)d_in[0];   // (B,N,D) f32
    const int*   t      = (const int*)d_in[1];     // (B,) i32
    const float* W      = (const float*)d_in[2];   // (E,D) f32
    const float* bg     = (const float*)d_in[3];   // (E,) f32
    float*       out    = (float*)d_out;           // (B,N,E) f32

    const size_t smem_bytes = (size_t)SMEM_FLOATS * sizeof(float);  // 90624 B
    cudaFuncSetAttribute(router_kernel,
                         cudaFuncAttributeMaxDynamicSharedMemorySize,
                         (int)smem_bytes);

    int n_tokens = in_sizes[0] / DDIM;             // 65536
    dim3 grid(n_tokens / NT);                      // 256 blocks
    router_kernel<<<grid, 256, smem_bytes>>>(tokens, t, W, bg, out);
}